// round 1
// baseline (speedup 1.0000x reference)
#include <cuda_runtime.h>

#define Bsz   8
#define Cch   192
#define Himg  224
#define Wimg  224
#define Pw    7
#define NHEAD 6
#define HDIM  32
#define WGRID 32
#define NWIN  1024
#define PPp   49
#define Mrows 401408    // Bsz*NWIN*PPp
#define HWSZ  50176     // Himg*Wimg

// scratch (device globals — no allocations allowed)
static __device__ float g_xw[(size_t)Mrows * Cch];        // 308 MB
static __device__ float g_qkv[(size_t)Mrows * 3 * Cch];   // 925 MB
static __device__ float g_attn[(size_t)Mrows * Cch];      // 308 MB
static __device__ float g_out2[(size_t)Mrows * Cch];      // 308 MB

__device__ __forceinline__ int m_of(int b, int hw) {
    int h = hw / Wimg;
    int w = hw - h * Wimg;
    int wi = h / Pw, pi = h - wi * Pw;
    int wj = w / Pw, pj = w - wj * Pw;
    return ((b * WGRID + wi) * WGRID + wj) * PPp + pi * Pw + pj;
}

// x (b,c,H,W) -> xw[m][c], m = window-token order
__global__ void k_gather(const float* __restrict__ x, float* __restrict__ xw) {
    __shared__ float tile[32][33];
    int hw0 = blockIdx.x << 5;
    int c0  = blockIdx.y << 5;
    int b   = blockIdx.z;
    int tx = threadIdx.x, ty = threadIdx.y;
    const float* xb = x + (size_t)b * Cch * HWSZ;
#pragma unroll
    for (int it = 0; it < 4; it++) {
        int c = c0 + ty + it * 8;
        tile[ty + it * 8][tx] = xb[(size_t)c * HWSZ + hw0 + tx];
    }
    __syncthreads();
#pragma unroll
    for (int it = 0; it < 4; it++) {
        int hw = hw0 + ty + it * 8;
        int m = m_of(b, hw);
        xw[(size_t)m * Cch + c0 + tx] = tile[tx][ty + it * 8];
    }
}

// out2[m][c] -> out (b,c,H,W)
__global__ void k_scatter(const float* __restrict__ out2, float* __restrict__ out) {
    __shared__ float tile[32][33];
    int hw0 = blockIdx.x << 5;
    int c0  = blockIdx.y << 5;
    int b   = blockIdx.z;
    int tx = threadIdx.x, ty = threadIdx.y;
#pragma unroll
    for (int it = 0; it < 4; it++) {
        int hw = hw0 + ty + it * 8;
        int m = m_of(b, hw);
        tile[ty + it * 8][tx] = out2[(size_t)m * Cch + c0 + tx];
    }
    __syncthreads();
    float* ob = out + (size_t)b * Cch * HWSZ;
#pragma unroll
    for (int it = 0; it < 4; it++) {
        int c = c0 + ty + it * 8;
        ob[(size_t)c * HWSZ + hw0 + tx] = tile[tx][ty + it * 8];
    }
}

// C[m][n] = sum_k A[m][k] * Wt[n][k] + bias[n]
// BM=128 BN=64 BK=16, 128 threads, 8x8 per thread. M%128==0, N%64==0, K=192.
__global__ void __launch_bounds__(128)
k_gemm(const float* __restrict__ A, const float* __restrict__ Wt,
       const float* __restrict__ bias, float* __restrict__ Cmat, int N) {
    const int K = Cch;
    __shared__ float As[16][128];
    __shared__ float Bs[16][64];
    int bm = blockIdx.y << 7;
    int bn = blockIdx.x << 6;
    int tid = threadIdx.x;
    int tx = tid & 7;    // n
    int ty = tid >> 3;   // m (0..15)

    float acc[8][8];
#pragma unroll
    for (int i = 0; i < 8; i++)
#pragma unroll
        for (int j = 0; j < 8; j++) acc[i][j] = 0.f;

    for (int k0 = 0; k0 < K; k0 += 16) {
        __syncthreads();
#pragma unroll
        for (int u = 0; u < 4; u++) {
            int f = tid + u * 128;
            int r = f >> 2, c = f & 3;
            float4 av = __ldg((const float4*)(A + (size_t)(bm + r) * K + k0 + c * 4));
            As[c * 4 + 0][r] = av.x;
            As[c * 4 + 1][r] = av.y;
            As[c * 4 + 2][r] = av.z;
            As[c * 4 + 3][r] = av.w;
        }
#pragma unroll
        for (int u = 0; u < 2; u++) {
            int f = tid + u * 128;
            int r = f >> 2, c = f & 3;
            float4 bv = __ldg((const float4*)(Wt + (size_t)(bn + r) * K + k0 + c * 4));
            Bs[c * 4 + 0][r] = bv.x;
            Bs[c * 4 + 1][r] = bv.y;
            Bs[c * 4 + 2][r] = bv.z;
            Bs[c * 4 + 3][r] = bv.w;
        }
        __syncthreads();
#pragma unroll
        for (int k = 0; k < 16; k++) {
            float4 a0 = *(const float4*)&As[k][ty * 8];
            float4 a1 = *(const float4*)&As[k][ty * 8 + 4];
            float4 b0 = *(const float4*)&Bs[k][tx * 8];
            float4 b1 = *(const float4*)&Bs[k][tx * 8 + 4];
            float a[8] = {a0.x, a0.y, a0.z, a0.w, a1.x, a1.y, a1.z, a1.w};
            float bb[8] = {b0.x, b0.y, b0.z, b0.w, b1.x, b1.y, b1.z, b1.w};
#pragma unroll
            for (int i = 0; i < 8; i++)
#pragma unroll
                for (int j = 0; j < 8; j++) acc[i][j] += a[i] * bb[j];
        }
    }

    float bv[8];
#pragma unroll
    for (int j = 0; j < 8; j++) bv[j] = bias[bn + tx * 8 + j];
#pragma unroll
    for (int i = 0; i < 8; i++) {
        float4 r0, r1;
        r0.x = acc[i][0] + bv[0]; r0.y = acc[i][1] + bv[1];
        r0.z = acc[i][2] + bv[2]; r0.w = acc[i][3] + bv[3];
        r1.x = acc[i][4] + bv[4]; r1.y = acc[i][5] + bv[5];
        r1.z = acc[i][6] + bv[6]; r1.w = acc[i][7] + bv[7];
        size_t off = (size_t)(bm + ty * 8 + i) * N + bn + tx * 8;
        *(float4*)(Cmat + off) = r0;
        *(float4*)(Cmat + off + 4) = r1;
    }
}

// one block per (b*NWIN+win)*NHEAD+head; 64 threads, thread i<49 owns row i
__global__ void __launch_bounds__(64)
k_attn(const float* __restrict__ qkv, float* __restrict__ attn,
       const float* __restrict__ rel_pos) {
    int blk = blockIdx.x;
    int head = blk % NHEAD;
    int win = blk / NHEAD;       // b*NWIN + w
    int base = win * PPp;        // row base in M
    int tid = threadIdx.x;

    __shared__ float qs[PPp * HDIM];
    __shared__ float ks[PPp * HDIM];
    __shared__ float vs[PPp * HDIM];
    __shared__ float sb[169];

    const size_t rowb = (size_t)base * 576;
    int toff = head * HDIM;
    for (int idx = tid; idx < PPp * HDIM; idx += 64) {
        int r = idx >> 5, d = idx & 31;
        size_t g = rowb + (size_t)r * 576 + toff + d;
        qs[idx] = qkv[g];
        ks[idx] = qkv[g + 192];
        vs[idx] = qkv[g + 384];
    }
    for (int idx = tid; idx < 169; idx += 64) sb[idx] = rel_pos[head * 169 + idx];
    __syncthreads();

    int i = tid;
    if (i < PPp) {
        float q[HDIM];
        const float4* q4 = (const float4*)(qs + i * HDIM);
#pragma unroll
        for (int t = 0; t < 8; t++) {
            float4 v = q4[t];
            q[t * 4 + 0] = v.x; q[t * 4 + 1] = v.y;
            q[t * 4 + 2] = v.z; q[t * 4 + 3] = v.w;
        }
        int ii = i / 7, ij = i - (i / 7) * 7;
        const float scale = 0.17677669529663687f;  // 32^-0.5
        float sim[PPp];
#pragma unroll
        for (int j = 0; j < PPp; j++) {
            const float4* k4 = (const float4*)(ks + j * HDIM);
            float acc = 0.f;
#pragma unroll
            for (int t = 0; t < 8; t++) {
                float4 kv = k4[t];
                acc += q[t * 4 + 0] * kv.x + q[t * 4 + 1] * kv.y
                     + q[t * 4 + 2] * kv.z + q[t * 4 + 3] * kv.w;
            }
            int ri = ii - j / 7 + 6;
            int rj = ij - (j - (j / 7) * 7) + 6;
            sim[j] = acc * scale + sb[ri * 13 + rj];
        }
        float mx = sim[0];
#pragma unroll
        for (int j = 1; j < PPp; j++) mx = fmaxf(mx, sim[j]);
        float sum = 0.f;
#pragma unroll
        for (int j = 0; j < PPp; j++) {
            sim[j] = __expf(sim[j] - mx);
            sum += sim[j];
        }
        float inv = 1.f / sum;
#pragma unroll
        for (int j = 0; j < PPp; j++) sim[j] *= inv;

        float4 oacc[8];
#pragma unroll
        for (int t = 0; t < 8; t++) oacc[t] = make_float4(0.f, 0.f, 0.f, 0.f);
#pragma unroll
        for (int j = 0; j < PPp; j++) {
            float pj = sim[j];
            const float4* v4 = (const float4*)(vs + j * HDIM);
#pragma unroll
            for (int t = 0; t < 8; t++) {
                float4 vv = v4[t];
                oacc[t].x += pj * vv.x;
                oacc[t].y += pj * vv.y;
                oacc[t].z += pj * vv.z;
                oacc[t].w += pj * vv.w;
            }
        }
        // stage own output row back into qs (only owner thread ever touches row i)
        float4* o4 = (float4*)(qs + i * HDIM);
#pragma unroll
        for (int t = 0; t < 8; t++) o4[t] = oacc[t];
    }
    __syncthreads();
    for (int idx = tid; idx < PPp * HDIM; idx += 64) {
        int r = idx >> 5, d = idx & 31;
        attn[((size_t)(base + r)) * Cch + toff + d] = qs[idx];
    }
}

extern "C" void kernel_launch(void* const* d_in, const int* in_sizes, int n_in,
                              void* d_out, int out_size) {
    const float* x       = (const float*)d_in[0];
    const float* w_qkv   = (const float*)d_in[1];
    const float* b_qkv   = (const float*)d_in[2];
    const float* rel_pos = (const float*)d_in[3];
    const float* w_out   = (const float*)d_in[4];
    const float* b_out   = (const float*)d_in[5];
    float* out = (float*)d_out;

    float *p_xw, *p_qkv, *p_attn, *p_out2;
    cudaGetSymbolAddress((void**)&p_xw, g_xw);
    cudaGetSymbolAddress((void**)&p_qkv, g_qkv);
    cudaGetSymbolAddress((void**)&p_attn, g_attn);
    cudaGetSymbolAddress((void**)&p_out2, g_out2);

    dim3 tb(32, 8);
    dim3 tg(HWSZ / 32, Cch / 32, Bsz);
    k_gather<<<tg, tb>>>(x, p_xw);
    k_gemm<<<dim3(576 / 64, Mrows / 128), 128>>>(p_xw, w_qkv, b_qkv, p_qkv, 576);
    k_attn<<<(Mrows / PPp) * NHEAD, 64>>>(p_qkv, p_attn, rel_pos);
    k_gemm<<<dim3(192 / 64, Mrows / 128), 128>>>(p_attn, w_out, b_out, p_out2, 192);
    k_scatter<<<tg, tb>>>(p_out2, out);
}

// round 3
// speedup vs baseline: 1.7917x; 1.7917x over previous
#include <cuda_runtime.h>
#include <cstdint>

#define Bsz   8
#define Cch   192
#define Himg  224
#define Wimg  224
#define Pw    7
#define NHEAD 6
#define HDIM  32
#define WGRID 32
#define NWIN  1024
#define PPp   49
#define Mrows 401408    // Bsz*NWIN*PPp
#define HWSZ  50176     // Himg*Wimg

// scratch (device globals — no allocations allowed)
static __device__ float g_xw[(size_t)Mrows * Cch];
static __device__ float g_qkv[(size_t)Mrows * 3 * Cch];
static __device__ float g_attn[(size_t)Mrows * Cch];
static __device__ float g_out2[(size_t)Mrows * Cch];

// ───────────────────────── helpers ─────────────────────────
__device__ __forceinline__ uint32_t f2tf(float f) {
    uint32_t u;
    asm("cvt.rna.tf32.f32 %0, %1;" : "=r"(u) : "f"(f));
    return u;
}
__device__ __forceinline__ void mma_m16n8k8(float* c, const uint32_t* a, const uint32_t* b) {
    asm volatile(
        "mma.sync.aligned.m16n8k8.row.col.f32.tf32.tf32.f32 "
        "{%0,%1,%2,%3}, {%4,%5,%6,%7}, {%8,%9}, {%0,%1,%2,%3};"
        : "+f"(c[0]), "+f"(c[1]), "+f"(c[2]), "+f"(c[3])
        : "r"(a[0]), "r"(a[1]), "r"(a[2]), "r"(a[3]), "r"(b[0]), "r"(b[1]));
}
__device__ __forceinline__ void cp16(uint32_t dst, const float* src) {
    asm volatile("cp.async.cg.shared.global [%0], [%1], 16;" :: "r"(dst), "l"(src));
}
#define CP_COMMIT() asm volatile("cp.async.commit_group;" ::: "memory")
#define CP_WAIT(n)  asm volatile("cp.async.wait_group %0;" :: "n"(n) : "memory")

// ───────────────────────── transposes ─────────────────────────
__device__ __forceinline__ int m_of(int b, int hw) {
    int h = hw / Wimg;
    int w = hw - h * Wimg;
    int wi = h / Pw, pi = h - wi * Pw;
    int wj = w / Pw, pj = w - wj * Pw;
    return ((b * WGRID + wi) * WGRID + wj) * PPp + pi * Pw + pj;
}

__global__ void k_gather(const float* __restrict__ x, float* __restrict__ xw) {
    __shared__ float tile[32][33];
    int hw0 = blockIdx.x << 5, c0 = blockIdx.y << 5, b = blockIdx.z;
    int tx = threadIdx.x, ty = threadIdx.y;
    const float* xb = x + (size_t)b * Cch * HWSZ;
#pragma unroll
    for (int it = 0; it < 4; it++) {
        int c = c0 + ty + it * 8;
        tile[ty + it * 8][tx] = xb[(size_t)c * HWSZ + hw0 + tx];
    }
    __syncthreads();
#pragma unroll
    for (int it = 0; it < 4; it++) {
        int hw = hw0 + ty + it * 8;
        int m = m_of(b, hw);
        xw[(size_t)m * Cch + c0 + tx] = tile[tx][ty + it * 8];
    }
}

__global__ void k_scatter(const float* __restrict__ out2, float* __restrict__ out) {
    __shared__ float tile[32][33];
    int hw0 = blockIdx.x << 5, c0 = blockIdx.y << 5, b = blockIdx.z;
    int tx = threadIdx.x, ty = threadIdx.y;
#pragma unroll
    for (int it = 0; it < 4; it++) {
        int hw = hw0 + ty + it * 8;
        int m = m_of(b, hw);
        tile[ty + it * 8][tx] = out2[(size_t)m * Cch + c0 + tx];
    }
    __syncthreads();
    float* ob = out + (size_t)b * Cch * HWSZ;
#pragma unroll
    for (int it = 0; it < 4; it++) {
        int c = c0 + ty + it * 8;
        ob[(size_t)c * HWSZ + hw0 + tx] = tile[tx][ty + it * 8];
    }
}

// ───────────────────────── TF32 mma.sync GEMM ─────────────────────────
// C[m][n] = sum_k A[m][k] * Wt[n][k] + bias[n].  K = 192.
// BM=128, BN=64, BK=16, 256 threads. Warp grid 4(M) x 2(N), warp tile 32x32.
#define GBM 128
#define GBN 64
#define GBK 16
#define KTOT 192
#define KTILES 12
#define ASTR 20          // padded row stride (floats) — conflict-free frag loads
#define ASZ (GBM * ASTR) // 2560 floats
#define BSZ (GBN * ASTR) // 1280 floats

__global__ void __launch_bounds__(256)
k_gemm_mma(const float* __restrict__ A, const float* __restrict__ Wt,
           const float* __restrict__ bias, float* __restrict__ C, int Ntot) {
    __shared__ float As[2][ASZ];
    __shared__ float Bs[2][BSZ];

    int tid = threadIdx.x;
    int wid = tid >> 5, lane = tid & 31;
    int gp = lane >> 2, tg = lane & 3;
    int wm = wid & 3, wn = wid >> 2;          // 4 x 2 warp grid
    size_t bm = (size_t)blockIdx.y * GBM;
    int bn = blockIdx.x * GBN;

    // load assignments
    int am0 = tid >> 2, akq = tid & 3;        // A: rows tid>>2 and +64
    int bn0 = tid >> 2;                        // B: row tid>>2 (256 = 64*4)

    const float* Ag0 = A + (bm + am0) * KTOT + akq * 4;
    const float* Ag1 = A + (bm + am0 + 64) * KTOT + akq * 4;
    const float* Bg  = Wt + (size_t)(bn + bn0) * KTOT + akq * 4;

    uint32_t sA0 = (uint32_t)__cvta_generic_to_shared(&As[0][am0 * ASTR + akq * 4]);
    uint32_t sA1 = (uint32_t)__cvta_generic_to_shared(&As[0][(am0 + 64) * ASTR + akq * 4]);
    uint32_t sB  = (uint32_t)__cvta_generic_to_shared(&Bs[0][bn0 * ASTR + akq * 4]);
    const uint32_t bufA = ASZ * 4, bufB = BSZ * 4;

    float acc[2][4][4];
#pragma unroll
    for (int mt = 0; mt < 2; mt++)
#pragma unroll
        for (int nt = 0; nt < 4; nt++)
#pragma unroll
            for (int r = 0; r < 4; r++) acc[mt][nt][r] = 0.f;

    // prologue: tile 0 -> buf 0
    cp16(sA0, Ag0); cp16(sA1, Ag1); cp16(sB, Bg);
    CP_COMMIT();

    const float* as_warp = &As[0][(wm * 32 + gp) * ASTR + tg];
    const float* bs_warp = &Bs[0][(wn * 32 + gp) * ASTR + tg];

#pragma unroll 1
    for (int t = 0; t < KTILES; t++) {
        int buf = t & 1;
        if (t + 1 < KTILES) {
            int k0 = (t + 1) * GBK;
            int nb = (t + 1) & 1;
            cp16(sA0 + nb * bufA, Ag0 + k0);
            cp16(sA1 + nb * bufA, Ag1 + k0);
            cp16(sB + nb * bufB, Bg + k0);
            CP_COMMIT();
            CP_WAIT(1);
        } else {
            CP_WAIT(0);
        }
        __syncthreads();

        const float* as = as_warp + buf * ASZ;
        const float* bs = bs_warp + buf * BSZ;
#pragma unroll
        for (int ks = 0; ks < 2; ks++) {
            uint32_t a[2][4], b[4][2];
#pragma unroll
            for (int mt = 0; mt < 2; mt++) {
                const float* p = as + mt * 16 * ASTR + ks * 8;
                a[mt][0] = f2tf(p[0]);
                a[mt][1] = f2tf(p[8 * ASTR]);
                a[mt][2] = f2tf(p[4]);
                a[mt][3] = f2tf(p[8 * ASTR + 4]);
            }
#pragma unroll
            for (int nt = 0; nt < 4; nt++) {
                const float* p = bs + nt * 8 * ASTR + ks * 8;
                b[nt][0] = f2tf(p[0]);
                b[nt][1] = f2tf(p[4]);
            }
#pragma unroll
            for (int mt = 0; mt < 2; mt++)
#pragma unroll
                for (int nt = 0; nt < 4; nt++)
                    mma_m16n8k8(acc[mt][nt], a[mt], b[nt]);
        }
        __syncthreads();
    }

    // epilogue
#pragma unroll
    for (int mt = 0; mt < 2; mt++) {
        int row = (int)bm + wm * 32 + mt * 16 + gp;
#pragma unroll
        for (int nt = 0; nt < 4; nt++) {
            int col = bn + wn * 32 + nt * 8 + tg * 2;
            float b0 = bias[col], b1 = bias[col + 1];
            float2 v0 = make_float2(acc[mt][nt][0] + b0, acc[mt][nt][1] + b1);
            float2 v1 = make_float2(acc[mt][nt][2] + b0, acc[mt][nt][3] + b1);
            *(float2*)(C + (size_t)row * Ntot + col) = v0;
            *(float2*)(C + (size_t)(row + 8) * Ntot + col) = v1;
        }
    }
}

// ───────────────────────── attention ─────────────────────────
__global__ void __launch_bounds__(64)
k_attn(const float* __restrict__ qkv, float* __restrict__ attn,
       const float* __restrict__ rel_pos) {
    int blk = blockIdx.x;
    int head = blk % NHEAD;
    int win = blk / NHEAD;
    int base = win * PPp;
    int tid = threadIdx.x;

    __shared__ float qs[PPp * HDIM];
    __shared__ float ks[PPp * HDIM];
    __shared__ float vs[PPp * HDIM];
    __shared__ float sb[169];

    const size_t rowb = (size_t)base * 576;
    int toff = head * HDIM;
    for (int idx = tid; idx < PPp * HDIM; idx += 64) {
        int r = idx >> 5, d = idx & 31;
        size_t g = rowb + (size_t)r * 576 + toff + d;
        qs[idx] = qkv[g];
        ks[idx] = qkv[g + 192];
        vs[idx] = qkv[g + 384];
    }
    for (int idx = tid; idx < 169; idx += 64) sb[idx] = rel_pos[head * 169 + idx];
    __syncthreads();

    int i = tid;
    if (i < PPp) {
        float q[HDIM];
        const float4* q4 = (const float4*)(qs + i * HDIM);
#pragma unroll
        for (int t = 0; t < 8; t++) {
            float4 v = q4[t];
            q[t * 4 + 0] = v.x; q[t * 4 + 1] = v.y;
            q[t * 4 + 2] = v.z; q[t * 4 + 3] = v.w;
        }
        int ii = i / 7, ij = i - (i / 7) * 7;
        const float scale = 0.17677669529663687f;
        float sim[PPp];
#pragma unroll
        for (int j = 0; j < PPp; j++) {
            const float4* k4 = (const float4*)(ks + j * HDIM);
            float acc = 0.f;
#pragma unroll
            for (int t = 0; t < 8; t++) {
                float4 kv = k4[t];
                acc += q[t * 4 + 0] * kv.x + q[t * 4 + 1] * kv.y
                     + q[t * 4 + 2] * kv.z + q[t * 4 + 3] * kv.w;
            }
            int ri = ii - j / 7 + 6;
            int rj = ij - (j - (j / 7) * 7) + 6;
            sim[j] = acc * scale + sb[ri * 13 + rj];
        }
        float mx = sim[0];
#pragma unroll
        for (int j = 1; j < PPp; j++) mx = fmaxf(mx, sim[j]);
        float sum = 0.f;
#pragma unroll
        for (int j = 0; j < PPp; j++) {
            sim[j] = __expf(sim[j] - mx);
            sum += sim[j];
        }
        float inv = 1.f / sum;
#pragma unroll
        for (int j = 0; j < PPp; j++) sim[j] *= inv;

        float4 oacc[8];
#pragma unroll
        for (int t = 0; t < 8; t++) oacc[t] = make_float4(0.f, 0.f, 0.f, 0.f);
#pragma unroll
        for (int j = 0; j < PPp; j++) {
            float pj = sim[j];
            const float4* v4 = (const float4*)(vs + j * HDIM);
#pragma unroll
            for (int t = 0; t < 8; t++) {
                float4 vv = v4[t];
                oacc[t].x += pj * vv.x;
                oacc[t].y += pj * vv.y;
                oacc[t].z += pj * vv.z;
                oacc[t].w += pj * vv.w;
            }
        }
        float4* o4 = (float4*)(qs + i * HDIM);
#pragma unroll
        for (int t = 0; t < 8; t++) o4[t] = oacc[t];
    }
    __syncthreads();
    for (int idx = tid; idx < PPp * HDIM; idx += 64) {
        int r = idx >> 5, d = idx & 31;
        attn[((size_t)(base + r)) * Cch + toff + d] = qs[idx];
    }
}

// ───────────────────────── launch ─────────────────────────
extern "C" void kernel_launch(void* const* d_in, const int* in_sizes, int n_in,
                              void* d_out, int out_size) {
    const float* x       = (const float*)d_in[0];
    const float* w_qkv   = (const float*)d_in[1];
    const float* b_qkv   = (const float*)d_in[2];
    const float* rel_pos = (const float*)d_in[3];
    const float* w_out   = (const float*)d_in[4];
    const float* b_out   = (const float*)d_in[5];
    float* out = (float*)d_out;

    float *p_xw, *p_qkv, *p_attn, *p_out2;
    cudaGetSymbolAddress((void**)&p_xw, g_xw);
    cudaGetSymbolAddress((void**)&p_qkv, g_qkv);
    cudaGetSymbolAddress((void**)&p_attn, g_attn);
    cudaGetSymbolAddress((void**)&p_out2, g_out2);

    dim3 tb(32, 8);
    dim3 tg(HWSZ / 32, Cch / 32, Bsz);
    k_gather<<<tg, tb>>>(x, p_xw);
    k_gemm_mma<<<dim3(576 / GBN, Mrows / GBM), 256>>>(p_xw, w_qkv, b_qkv, p_qkv, 576);
    k_attn<<<(Mrows / PPp) * NHEAD, 64>>>(p_qkv, p_attn, rel_pos);
    k_gemm_mma<<<dim3(192 / GBN, Mrows / GBM), 256>>>(p_attn, w_out, b_out, p_out2, 192);
    k_scatter<<<tg, tb>>>(p_out2, out);
}

// round 4
// speedup vs baseline: 1.8580x; 1.0370x over previous
#include <cuda_runtime.h>
#include <cstdint>

#define Bsz   8
#define Cch   192
#define Himg  224
#define Wimg  224
#define Pw    7
#define NHEAD 6
#define HDIM  32
#define WGRID 32
#define NWIN  1024
#define PPp   49
#define Mrows 401408    // Bsz*NWIN*PPp
#define HWSZ  50176     // Himg*Wimg

typedef unsigned long long u64t;

// scratch (device globals — no allocations allowed)
static __device__ float g_xw[(size_t)Mrows * Cch];
static __device__ float g_qkv[(size_t)Mrows * 3 * Cch];
static __device__ float g_attn[(size_t)Mrows * Cch];
static __device__ float g_out2[(size_t)Mrows * Cch];
static __device__ float g_wqkv[576 * 192];   // tf32-rounded weights
static __device__ float g_wout[192 * 192];

// ───────────────────────── helpers ─────────────────────────
__device__ __forceinline__ uint32_t f2tf(float f) {
    uint32_t u;
    asm("cvt.rna.tf32.f32 %0, %1;" : "=r"(u) : "f"(f));
    return u;
}
__device__ __forceinline__ float f2tf_f(float f) {
    return __uint_as_float(f2tf(f));
}
__device__ __forceinline__ u64t fma2(u64t a, u64t b, u64t c) {
    u64t d;
    asm("fma.rn.f32x2 %0, %1, %2, %3;" : "=l"(d) : "l"(a), "l"(b), "l"(c));
    return d;
}
__device__ __forceinline__ void mma_m16n8k8(float* c, const uint32_t* a, const uint32_t* b) {
    asm volatile(
        "mma.sync.aligned.m16n8k8.row.col.f32.tf32.tf32.f32 "
        "{%0,%1,%2,%3}, {%4,%5,%6,%7}, {%8,%9}, {%0,%1,%2,%3};"
        : "+f"(c[0]), "+f"(c[1]), "+f"(c[2]), "+f"(c[3])
        : "r"(a[0]), "r"(a[1]), "r"(a[2]), "r"(a[3]), "r"(b[0]), "r"(b[1]));
}
__device__ __forceinline__ void cp16(uint32_t dst, const float* src) {
    asm volatile("cp.async.cg.shared.global [%0], [%1], 16;" :: "r"(dst), "l"(src));
}
#define CP_COMMIT() asm volatile("cp.async.commit_group;" ::: "memory")
#define CP_WAIT(n)  asm volatile("cp.async.wait_group %0;" :: "n"(n) : "memory")

// ───────────────────────── weight pre-round ─────────────────────────
__global__ void k_round(const float* __restrict__ w, float* __restrict__ o, int n) {
    int i = blockIdx.x * 256 + threadIdx.x;
    if (i < n) o[i] = f2tf_f(w[i]);
}

// ───────────────────────── transposes ─────────────────────────
__device__ __forceinline__ int m_of(int b, int hw) {
    int h = hw / Wimg;
    int w = hw - h * Wimg;
    int wi = h / Pw, pi = h - wi * Pw;
    int wj = w / Pw, pj = w - wj * Pw;
    return ((b * WGRID + wi) * WGRID + wj) * PPp + pi * Pw + pj;
}

__global__ void k_gather(const float* __restrict__ x, float* __restrict__ xw) {
    __shared__ float tile[32][33];
    int hw0 = blockIdx.x << 5, c0 = blockIdx.y << 5, b = blockIdx.z;
    int tx = threadIdx.x, ty = threadIdx.y;
    const float* xb = x + (size_t)b * Cch * HWSZ;
#pragma unroll
    for (int it = 0; it < 4; it++) {
        int c = c0 + ty + it * 8;
        tile[ty + it * 8][tx] = xb[(size_t)c * HWSZ + hw0 + tx];
    }
    __syncthreads();
#pragma unroll
    for (int it = 0; it < 4; it++) {
        int hw = hw0 + ty + it * 8;
        int m = m_of(b, hw);
        // round to tf32 here so the GEMM can skip per-fragment cvt
        xw[(size_t)m * Cch + c0 + tx] = f2tf_f(tile[tx][ty + it * 8]);
    }
}

__global__ void k_scatter(const float* __restrict__ out2, float* __restrict__ out) {
    __shared__ float tile[32][33];
    int hw0 = blockIdx.x << 5, c0 = blockIdx.y << 5, b = blockIdx.z;
    int tx = threadIdx.x, ty = threadIdx.y;
#pragma unroll
    for (int it = 0; it < 4; it++) {
        int hw = hw0 + ty + it * 8;
        int m = m_of(b, hw);
        tile[ty + it * 8][tx] = out2[(size_t)m * Cch + c0 + tx];
    }
    __syncthreads();
    float* ob = out + (size_t)b * Cch * HWSZ;
#pragma unroll
    for (int it = 0; it < 4; it++) {
        int c = c0 + ty + it * 8;
        ob[(size_t)c * HWSZ + hw0 + tx] = tile[tx][ty + it * 8];
    }
}

// ───────────────────────── TF32 mma.sync GEMM ─────────────────────────
// Operands in memory are ALREADY tf32-rounded. No cvt in the mainloop.
#define GBM 128
#define GBN 64
#define GBK 16
#define KTOT 192
#define KTILES 12
#define ASTR 20
#define ASZ (GBM * ASTR)
#define BSZ (GBN * ASTR)

__global__ void __launch_bounds__(256)
k_gemm_mma(const float* __restrict__ A, const float* __restrict__ Wt,
           const float* __restrict__ bias, float* __restrict__ C, int Ntot) {
    __shared__ float As[2][ASZ];
    __shared__ float Bs[2][BSZ];

    int tid = threadIdx.x;
    int wid = tid >> 5, lane = tid & 31;
    int gp = lane >> 2, tg = lane & 3;
    int wm = wid & 3, wn = wid >> 2;
    size_t bm = (size_t)blockIdx.y * GBM;
    int bn = blockIdx.x * GBN;

    int am0 = tid >> 2, akq = tid & 3;
    int bn0 = tid >> 2;

    const float* Ag0 = A + (bm + am0) * KTOT + akq * 4;
    const float* Ag1 = A + (bm + am0 + 64) * KTOT + akq * 4;
    const float* Bg  = Wt + (size_t)(bn + bn0) * KTOT + akq * 4;

    uint32_t sA0 = (uint32_t)__cvta_generic_to_shared(&As[0][am0 * ASTR + akq * 4]);
    uint32_t sA1 = (uint32_t)__cvta_generic_to_shared(&As[0][(am0 + 64) * ASTR + akq * 4]);
    uint32_t sB  = (uint32_t)__cvta_generic_to_shared(&Bs[0][bn0 * ASTR + akq * 4]);
    const uint32_t bufA = ASZ * 4, bufB = BSZ * 4;

    float acc[2][4][4];
#pragma unroll
    for (int mt = 0; mt < 2; mt++)
#pragma unroll
        for (int nt = 0; nt < 4; nt++)
#pragma unroll
            for (int r = 0; r < 4; r++) acc[mt][nt][r] = 0.f;

    cp16(sA0, Ag0); cp16(sA1, Ag1); cp16(sB, Bg);
    CP_COMMIT();

    const float* as_warp = &As[0][(wm * 32 + gp) * ASTR + tg];
    const float* bs_warp = &Bs[0][(wn * 32 + gp) * ASTR + tg];

#pragma unroll 1
    for (int t = 0; t < KTILES; t++) {
        int buf = t & 1;
        if (t + 1 < KTILES) {
            int k0 = (t + 1) * GBK;
            int nb = (t + 1) & 1;
            cp16(sA0 + nb * bufA, Ag0 + k0);
            cp16(sA1 + nb * bufA, Ag1 + k0);
            cp16(sB + nb * bufB, Bg + k0);
            CP_COMMIT();
            CP_WAIT(1);
        } else {
            CP_WAIT(0);
        }
        __syncthreads();

        const float* as = as_warp + buf * ASZ;
        const float* bs = bs_warp + buf * BSZ;
#pragma unroll
        for (int ks = 0; ks < 2; ks++) {
            uint32_t a[2][4], b[4][2];
#pragma unroll
            for (int mt = 0; mt < 2; mt++) {
                const float* p = as + mt * 16 * ASTR + ks * 8;
                a[mt][0] = __float_as_uint(p[0]);
                a[mt][1] = __float_as_uint(p[8 * ASTR]);
                a[mt][2] = __float_as_uint(p[4]);
                a[mt][3] = __float_as_uint(p[8 * ASTR + 4]);
            }
#pragma unroll
            for (int nt = 0; nt < 4; nt++) {
                const float* p = bs + nt * 8 * ASTR + ks * 8;
                b[nt][0] = __float_as_uint(p[0]);
                b[nt][1] = __float_as_uint(p[4]);
            }
#pragma unroll
            for (int mt = 0; mt < 2; mt++)
#pragma unroll
                for (int nt = 0; nt < 4; nt++)
                    mma_m16n8k8(acc[mt][nt], a[mt], b[nt]);
        }
        __syncthreads();
    }

#pragma unroll
    for (int mt = 0; mt < 2; mt++) {
        int row = (int)bm + wm * 32 + mt * 16 + gp;
#pragma unroll
        for (int nt = 0; nt < 4; nt++) {
            int col = bn + wn * 32 + nt * 8 + tg * 2;
            float b0 = bias[col], b1 = bias[col + 1];
            float2 v0 = make_float2(acc[mt][nt][0] + b0, acc[mt][nt][1] + b1);
            float2 v1 = make_float2(acc[mt][nt][2] + b0, acc[mt][nt][3] + b1);
            *(float2*)(C + (size_t)row * Ntot + col) = v0;
            *(float2*)(C + (size_t)(row + 8) * Ntot + col) = v1;
        }
    }
}

// ───────────────────────── attention (f32x2 packed) ─────────────────────────
__global__ void __launch_bounds__(64)
k_attn(const float* __restrict__ qkv, float* __restrict__ attn,
       const float* __restrict__ rel_pos) {
    int blk = blockIdx.x;
    int head = blk % NHEAD;
    int win = blk / NHEAD;
    int base = win * PPp;
    int tid = threadIdx.x;

    __shared__ __align__(16) float qs[PPp * HDIM];
    __shared__ __align__(16) float ks[PPp * HDIM];
    __shared__ __align__(16) float vs[PPp * HDIM];
    __shared__ float sb[169];

    const size_t rowb = (size_t)base * 576;
    int toff = head * HDIM;
    for (int idx = tid; idx < PPp * HDIM; idx += 64) {
        int r = idx >> 5, d = idx & 31;
        size_t g = rowb + (size_t)r * 576 + toff + d;
        qs[idx] = qkv[g];
        ks[idx] = qkv[g + 192];
        vs[idx] = qkv[g + 384];
    }
    for (int idx = tid; idx < 169; idx += 64) sb[idx] = rel_pos[head * 169 + idx];
    __syncthreads();

    int i = tid;
    if (i < PPp) {
        u64t q2[16];
        const u64t* qp = (const u64t*)(qs + i * HDIM);
#pragma unroll
        for (int t = 0; t < 16; t++) q2[t] = qp[t];

        int ii = i / 7, ij = i - (i / 7) * 7;
        const float scale = 0.17677669529663687f;
        float sim[PPp];
#pragma unroll
        for (int j = 0; j < PPp; j++) {
            const u64t* kp = (const u64t*)(ks + j * HDIM);
            u64t acc2 = 0ull;   // (0.0f, 0.0f)
#pragma unroll
            for (int t = 0; t < 16; t++) acc2 = fma2(q2[t], kp[t], acc2);
            float lo = __uint_as_float((uint32_t)acc2);
            float hi = __uint_as_float((uint32_t)(acc2 >> 32));
            int ri = ii - j / 7 + 6;
            int rj = ij - (j - (j / 7) * 7) + 6;
            sim[j] = (lo + hi) * scale + sb[ri * 13 + rj];
        }
        float mx = sim[0];
#pragma unroll
        for (int j = 1; j < PPp; j++) mx = fmaxf(mx, sim[j]);
        float sum = 0.f;
#pragma unroll
        for (int j = 0; j < PPp; j++) {
            sim[j] = __expf(sim[j] - mx);
            sum += sim[j];
        }
        float inv = 1.f / sum;
#pragma unroll
        for (int j = 0; j < PPp; j++) sim[j] *= inv;

        u64t o2[16];
#pragma unroll
        for (int t = 0; t < 16; t++) o2[t] = 0ull;
#pragma unroll
        for (int j = 0; j < PPp; j++) {
            u64t p2;
            uint32_t pb = __float_as_uint(sim[j]);
            asm("mov.b64 %0, {%1, %1};" : "=l"(p2) : "r"(pb));
            const u64t* vp = (const u64t*)(vs + j * HDIM);
#pragma unroll
            for (int t = 0; t < 16; t++) o2[t] = fma2(p2, vp[t], o2[t]);
        }
        u64t* op = (u64t*)(qs + i * HDIM);
#pragma unroll
        for (int t = 0; t < 16; t++) op[t] = o2[t];
    }
    __syncthreads();
    // store, rounded to tf32 so the out-proj GEMM skips cvt
    for (int idx = tid; idx < PPp * HDIM; idx += 64) {
        int r = idx >> 5, d = idx & 31;
        attn[((size_t)(base + r)) * Cch + toff + d] = f2tf_f(qs[idx]);
    }
}

// ───────────────────────── launch ─────────────────────────
extern "C" void kernel_launch(void* const* d_in, const int* in_sizes, int n_in,
                              void* d_out, int out_size) {
    const float* x       = (const float*)d_in[0];
    const float* w_qkv   = (const float*)d_in[1];
    const float* b_qkv   = (const float*)d_in[2];
    const float* rel_pos = (const float*)d_in[3];
    const float* w_out   = (const float*)d_in[4];
    const float* b_out   = (const float*)d_in[5];
    float* out = (float*)d_out;

    float *p_xw, *p_qkv, *p_attn, *p_out2, *p_wqkv, *p_wout;
    cudaGetSymbolAddress((void**)&p_xw, g_xw);
    cudaGetSymbolAddress((void**)&p_qkv, g_qkv);
    cudaGetSymbolAddress((void**)&p_attn, g_attn);
    cudaGetSymbolAddress((void**)&p_out2, g_out2);
    cudaGetSymbolAddress((void**)&p_wqkv, g_wqkv);
    cudaGetSymbolAddress((void**)&p_wout, g_wout);

    k_round<<<(576 * 192 + 255) / 256, 256>>>(w_qkv, p_wqkv, 576 * 192);
    k_round<<<(192 * 192 + 255) / 256, 256>>>(w_out, p_wout, 192 * 192);

    dim3 tb(32, 8);
    dim3 tg(HWSZ / 32, Cch / 32, Bsz);
    k_gather<<<tg, tb>>>(x, p_xw);
    k_gemm_mma<<<dim3(576 / GBN, Mrows / GBM), 256>>>(p_xw, p_wqkv, b_qkv, p_qkv, 576);
    k_attn<<<(Mrows / PPp) * NHEAD, 64>>>(p_qkv, p_attn, rel_pos);
    k_gemm_mma<<<dim3(192 / GBN, Mrows / GBM), 256>>>(p_attn, p_wout, b_out, p_out2, 192);
    k_scatter<<<tg, tb>>>(p_out2, out);
}